// round 2
// baseline (speedup 1.0000x reference)
#include <cuda_runtime.h>
#include <cstdint>
#include <math.h>

#define B_ 32
#define L_ 128
#define D_ 300
#define H_ 128
#define E_ 34
#define A_ 36
#define M_ (B_*L_)          // 4096
#define NXW 1024
#define ARG_OFF (B_*L_*E_)  // 139264

// ------------------------- scratch (no allocs allowed) -----------------------
__device__ float g_xw[M_*NXW];       // x@W_ih^T + b_ih + b_hh, both dirs
__device__ float g_hidden[M_*256];   // [h_f | h_b]
__device__ float g_base[M_*A_];      // hidden@argW_h^T + arg_b
__device__ float g_trig[M_*A_];      // hidden@argW_t^T
__device__ int   g_evp[M_];          // argmax(event_logits)

// ------------------------- helpers ------------------------------------------
__device__ __forceinline__ unsigned long long pack2(float lo, float hi){
    unsigned long long r;
    asm("mov.b64 %0, {%1, %2};" : "=l"(r) : "f"(lo), "f"(hi));
    return r;
}
__device__ __forceinline__ void unpack2(unsigned long long v, float& lo, float& hi){
    asm("mov.b64 {%0, %1}, %2;" : "=f"(lo), "=f"(hi) : "l"(v));
}
__device__ __forceinline__ unsigned long long fma2(unsigned long long a,
                                                   unsigned long long b,
                                                   unsigned long long c){
    unsigned long long d;
    asm("fma.rn.f32x2 %0, %1, %2, %3;" : "=l"(d) : "l"(a), "l"(b), "l"(c));
    return d;
}
__device__ __forceinline__ uint32_t smem_u32(const void* p){
    return (uint32_t)__cvta_generic_to_shared(p);
}
__device__ __forceinline__ uint32_t mapa_u32(uint32_t a, uint32_t r){
    uint32_t d;
    asm("mapa.shared::cluster.u32 %0, %1, %2;" : "=r"(d) : "r"(a), "r"(r));
    return d;
}
#define CLUSTER_SYNC_() do { \
    asm volatile("barrier.cluster.arrive.aligned;" ::: "memory"); \
    asm volatile("barrier.cluster.wait.aligned;"   ::: "memory"); \
} while(0)

// wait (acquire, cluster scope) on local mbarrier for given phase parity
__device__ __forceinline__ void mbar_wait_cluster(uint32_t addr, unsigned parity){
    asm volatile(
        "{\n\t"
        ".reg .pred P;\n\t"
        "WLOOP%=:\n\t"
        "mbarrier.try_wait.parity.acquire.cluster.shared::cta.b64 P, [%0], %1;\n\t"
        "@P bra WDONE%=;\n\t"
        "bra WLOOP%=;\n\t"
        "WDONE%=:\n\t"
        "}"
        :: "r"(addr), "r"(parity) : "memory");
}

// =============================================================================
// Kernel 1: xW = gather(emb, ids) @ [w_ih_f^T | w_ih_b^T] + (b_ih + b_hh)
// M=4096, N=1024, K=300.  128x128 tiles, 256 threads, 8x8 micro, f32x2 FMA.
// =============================================================================
__global__ __launch_bounds__(256) void gemm_xw_kernel(
    const int* __restrict__ ids, const float* __restrict__ emb,
    const float* __restrict__ wf, const float* __restrict__ wb,
    const float* __restrict__ bihf, const float* __restrict__ bhhf,
    const float* __restrict__ bihb, const float* __restrict__ bhhb)
{
    __shared__ float As[8][132];
    __shared__ float Bs[8][132];
    __shared__ int ids_s[128];

    int t  = threadIdx.x;
    int m0 = blockIdx.y * 128;
    int n0 = blockIdx.x * 128;

    const float* w;
    const float *b1, *b2;
    if (n0 < 512) { w = wf + (size_t)n0 * D_;        b1 = bihf + n0;        b2 = bhhf + n0; }
    else          { w = wb + (size_t)(n0-512) * D_;  b1 = bihb + (n0-512);  b2 = bhhb + (n0-512); }

    if (t < 128) ids_s[t] = ids[m0 + t];
    __syncthreads();

    int tx = t & 15, ty = t >> 4;
    unsigned long long acc[8][4];
#pragma unroll
    for (int r = 0; r < 8; r++)
#pragma unroll
        for (int p = 0; p < 4; p++) acc[r][p] = 0ull;

    int ai = t & 127, akk = (t >> 7) * 4;   // A loader: (row ai, kk akk..akk+3)
    int bj = t >> 3,  bkk = t & 7;          // B loader: (rows bj+32c, kk bkk)

    for (int k0 = 0; k0 < D_; k0 += 8) {
        const float* arow = emb + (size_t)ids_s[ai] * D_;
#pragma unroll
        for (int c = 0; c < 4; c++) {
            int kk = akk + c;
            As[kk][ai] = (k0 + kk < D_) ? arow[k0 + kk] : 0.f;
        }
#pragma unroll
        for (int c = 0; c < 4; c++) {
            int j = bj + 32 * c;
            Bs[bkk][j] = (k0 + bkk < D_) ? w[(size_t)j * D_ + k0 + bkk] : 0.f;
        }
        __syncthreads();
#pragma unroll
        for (int kk = 0; kk < 8; kk++) {
            float a_[8];
#pragma unroll
            for (int r = 0; r < 8; r++) a_[r] = As[kk][ty*8 + r];
            unsigned long long b2v[4];
            const float2* bp = (const float2*)&Bs[kk][tx*8];
#pragma unroll
            for (int p = 0; p < 4; p++) { float2 v = bp[p]; b2v[p] = pack2(v.x, v.y); }
#pragma unroll
            for (int r = 0; r < 8; r++) {
                unsigned long long a2 = pack2(a_[r], a_[r]);
#pragma unroll
                for (int p = 0; p < 4; p++) acc[r][p] = fma2(a2, b2v[p], acc[r][p]);
            }
        }
        __syncthreads();
    }

#pragma unroll
    for (int r = 0; r < 8; r++) {
        int m = m0 + ty*8 + r;
#pragma unroll
        for (int p = 0; p < 4; p++) {
            float lo, hi; unpack2(acc[r][p], lo, hi);
            int nlo = tx*8 + 2*p;
            g_xw[(size_t)m * NXW + n0 + nlo]     = lo + b1[nlo]   + b2[nlo];
            g_xw[(size_t)m * NXW + n0 + nlo + 1] = hi + b1[nlo+1] + b2[nlo+1];
        }
    }
}

// =============================================================================
// Kernel 2: BiLSTM recurrence.
// 16 clusters of 8 CTAs: cluster = (dir, batch-group of 4). CTA = 16 hidden
// units (64 gate rows). W_hh slice in registers as packed f32x2 (16 x ull).
// h exchanged per step via DSMEM; per-step sync via mbarrier (count=512:
// 64 updater threads x 8 CTAs, each arriving remotely with release.cluster
// ordering AFTER its own DSMEM h stores). No cluster.sync in the loop.
// =============================================================================
__global__ void __cluster_dims__(8,1,1) __launch_bounds__(256,1)
lstm_kernel(const float* __restrict__ whf, const float* __restrict__ whb)
{
    __shared__ __align__(16) float h_sm[2][4][132];   // [phase][batch][128+pad]
    __shared__ float z_sm[4][64];
    __shared__ __align__(8) unsigned long long mbar;

    int bx   = blockIdx.x;
    int cid  = bx >> 3, rank = bx & 7;
    int dir  = cid & 1,  bg  = cid >> 1;      // batches bg*4 .. bg*4+3
    int u0   = rank * 16;

    int t = threadIdx.x, lane = t & 31, warp = t >> 5;
    int rl = lane & 7, kq = lane >> 3;
    int row  = warp*8 + rl;                   // 0..63 local gate row
    int gate = row >> 4, uu = row & 15;
    int grow = gate*H_ + u0 + uu;             // global gate row 0..511

    const float* whh = dir ? whb : whf;
    unsigned long long w2[16];                // 32 weights packed as f32x2
    {
        const float4* wrow = (const float4*)(whh + (size_t)grow*H_ + kq*32);
#pragma unroll
        for (int i = 0; i < 8; i++) {
            float4 wv = wrow[i];
            w2[2*i]   = pack2(wv.x, wv.y);
            w2[2*i+1] = pack2(wv.z, wv.w);
        }
    }

    for (int idx = t; idx < 2*4*132; idx += 256) (&h_sm[0][0][0])[idx] = 0.f;
    if (t == 0) {
        asm volatile("mbarrier.init.shared.b64 [%0], %1;"
                     :: "r"(smem_u32(&mbar)), "r"(512) : "memory");
    }

    int ub = t >> 4, uuu = t & 15;            // updater role (t < 64)
    float c_reg = 0.f;

    CLUSTER_SYNC_();                          // barriers + zeroed h visible

    int xw_col = dir*512 + grow;
    uint32_t bar_a = smem_u32(&mbar);

    for (int s = 0; s < L_; s++) {
        int ph = s & 1;
        int tc = dir ? (L_-1-s) : s;

        // xw loads are barrier-independent: issue before the wait.
        float xwv0=0.f, xwv1=0.f, xwv2=0.f, xwv3=0.f;
        if (kq == 0) {
            size_t base = ((size_t)(bg*4)*L_ + tc) * NXW + xw_col;
            xwv0 = g_xw[base];
            xwv1 = g_xw[base + (size_t)L_*NXW];
            xwv2 = g_xw[base + (size_t)2*L_*NXW];
            xwv3 = g_xw[base + (size_t)3*L_*NXW];
        }

        if (s > 0) mbar_wait_cluster(bar_a, (unsigned)((s-1) & 1));

        float a[4];
#pragma unroll
        for (int b = 0; b < 4; b++) {
            unsigned long long acc = 0ull;
            const float4* hp = (const float4*)&h_sm[ph][b][kq*32];
#pragma unroll
            for (int i = 0; i < 8; i++) {
                float4 hv = hp[i];
                acc = fma2(w2[2*i],   pack2(hv.x, hv.y), acc);
                acc = fma2(w2[2*i+1], pack2(hv.z, hv.w), acc);
            }
            float lo, hi; unpack2(acc, lo, hi);
            a[b] = lo + hi;
        }
#pragma unroll
        for (int b = 0; b < 4; b++) {
            a[b] += __shfl_xor_sync(~0u, a[b], 8);
            a[b] += __shfl_xor_sync(~0u, a[b], 16);
        }

        if (kq == 0) {
            z_sm[0][row] = a[0] + xwv0;
            z_sm[1][row] = a[1] + xwv1;
            z_sm[2][row] = a[2] + xwv2;
            z_sm[3][row] = a[3] + xwv3;
        }
        __syncthreads();

        if (t < 64) {
            float zi = z_sm[ub][uuu],      zf = z_sm[ub][16 + uuu];
            float zg = z_sm[ub][32 + uuu], zo = z_sm[ub][48 + uuu];
            float ig = 1.f / (1.f + expf(-zi));
            float fg = 1.f / (1.f + expf(-zf));
            float gg = tanhf(zg);
            float og = 1.f / (1.f + expf(-zo));
            c_reg = fg * c_reg + ig * gg;
            float h = og * tanhf(c_reg);

            int k = u0 + uuu;
            uint32_t loc = smem_u32(&h_sm[ph ^ 1][ub][k]);
#pragma unroll
            for (int r = 0; r < 8; r++) {
                uint32_t ra = mapa_u32(loc, (uint32_t)r);
                asm volatile("st.shared::cluster.f32 [%0], %1;" :: "r"(ra), "f"(h));
            }
#pragma unroll
            for (int r = 0; r < 8; r++) {
                uint32_t ba = mapa_u32(bar_a, (uint32_t)r);
                asm volatile("mbarrier.arrive.release.cluster.shared::cluster.b64 _, [%0];"
                             :: "r"(ba) : "memory");
            }
            g_hidden[((size_t)((bg*4 + ub)*L_ + tc)) * 256 + dir*H_ + k] = h;
        }
        // no second __syncthreads: next-step mbarrier wait subsumes it
    }
    CLUSTER_SYNC_();   // drain in-flight remote stores before exit
}

// =============================================================================
// Kernel 3: fused head GEMM + event argmax.
// hidden[4096,256] @ W2^T, W2 rows = [event_w(34) | argW[:, :256](36) |
// argW[:,256:512](36)] -> 106 cols. Epilogue: argmax over 34 -> g_evp.
// =============================================================================
__global__ __launch_bounds__(256) void head_kernel(
    const float* __restrict__ ew, const float* __restrict__ eb,
    const float* __restrict__ aw, const float* __restrict__ ab,
    float* __restrict__ out)
{
    __shared__ float hsm[64][65];
    __shared__ float wsm[64][108];
    __shared__ float ev_sm[64][36];

    int t  = threadIdx.x;
    int m0 = blockIdx.x * 64;
    int ml = t >> 2, ng = t & 3;

    float acc[27];
#pragma unroll
    for (int c = 0; c < 27; c++) acc[c] = 0.f;

    for (int k0 = 0; k0 < 256; k0 += 64) {
        for (int idx = t; idx < 64*64; idx += 256) {
            int r = idx >> 6, c = idx & 63;
            hsm[r][c] = g_hidden[(size_t)(m0 + r)*256 + k0 + c];
        }
        for (int idx = t; idx < 64*108; idx += 256) {
            int kk = idx / 108, n = idx % 108;
            int k  = k0 + kk;
            float v = 0.f;
            if      (n < 34)  v = ew[(size_t)n*256 + k];
            else if (n < 70)  v = aw[(size_t)(n-34)*545 + k];
            else if (n < 106) v = aw[(size_t)(n-70)*545 + 256 + k];
            wsm[kk][n] = v;
        }
        __syncthreads();
#pragma unroll 8
        for (int kk = 0; kk < 64; kk++) {
            float hv = hsm[ml][kk];
#pragma unroll
            for (int c = 0; c < 27; c++) acc[c] += hv * wsm[kk][ng*27 + c];
        }
        __syncthreads();
    }

    int m = m0 + ml;
#pragma unroll
    for (int c = 0; c < 27; c++) {
        int n = ng*27 + c;
        if (n < 34) {
            float v = acc[c] + eb[n];
            out[(size_t)m*E_ + n] = v;
            ev_sm[ml][n] = v;
        }
        else if (n < 70)  g_base[(size_t)m*A_ + (n-34)] = acc[c] + ab[n-34];
        else if (n < 106) g_trig[(size_t)m*A_ + (n-70)] = acc[c];
    }
    __syncthreads();

    if (t < 64) {
        float bv = ev_sm[t][0]; int bi = 0;
#pragma unroll
        for (int e = 1; e < E_; e++) {
            float v = ev_sm[t][e];
            if (v > bv) { bv = v; bi = e; }
        }
        g_evp[m0 + t] = bi;
    }
}

// =============================================================================
// Kernel 4: scan. One warp per (b, l); g[b,l] is an independent 33-bit state.
// arg_logit[i] = base[b,l] + trig[b,i] + gW (incrementally maintained).
// ev_pred[b, 0..127] byte-packed into per-lane registers (shfl broadcast).
// =============================================================================
__global__ __launch_bounds__(128) void scan_kernel(
    const float* __restrict__ aw, float* __restrict__ out)
{
    __shared__ float wg[36*33];   // arg_w[:, 512:545]
    int t = threadIdx.x;
    for (int idx = t; idx < 36*33; idx += 128) {
        int a = idx / 33, c = idx % 33;
        wg[idx] = aw[(size_t)a*545 + 512 + c];
    }
    __syncthreads();

    int gw_id = blockIdx.x * 4 + (t >> 5);
    int lane  = t & 31;
    int b = gw_id >> 7, l = gw_id & 127;
    size_t bl = (size_t)(b*L_ + l);

    // byte-pack this batch's 128 ev_preds: lane j holds evp[b, 4j..4j+3]
    const int* evb = g_evp + b*L_ + lane*4;
    int ep4 = evb[0] | (evb[1] << 8) | (evb[2] << 16) | (evb[3] << 24);

    bool hi = lane < 4;
    float base0 = g_base[bl*A_ + lane];
    float base1 = hi ? g_base[bl*A_ + 32 + lane] : -3.4e38f;
    float gw0 = 0.f, gw1 = 0.f;
    unsigned long long gb = 0ull;
    float* oarg = out + ARG_OFF;

    for (int i = 0; i < L_; i++) {
        size_t bi_ = (size_t)(b*L_ + i);
        float t0 = g_trig[bi_*A_ + lane];
        float t1 = hi ? g_trig[bi_*A_ + 32 + lane] : 0.f;
        float v0 = base0 + t0 + gw0;
        float v1 = hi ? (base1 + t1 + gw1) : -3.4e38f;

        size_t ob = (bi_*L_ + l) * A_;
        oarg[ob + lane] = v0;
        if (hi) oarg[ob + 32 + lane] = v1;

        float bv = v0; int bidx = lane;
        if (hi && v1 > bv) { bv = v1; bidx = lane + 32; }
#pragma unroll
        for (int off = 16; off; off >>= 1) {
            float ov = __shfl_xor_sync(0xffffffffu, bv, off);
            int   oi = __shfl_xor_sync(0xffffffffu, bidx, off);
            if (ov > bv || (ov == bv && oi < bidx)) { bv = ov; bidx = oi; }
        }

        int ep = (__shfl_sync(0xffffffffu, ep4, i >> 2) >> ((i & 3) * 8)) & 0xff;
        if (ep > 0 && bidx > 0) {
            int col = ep - 1;
            if (!((gb >> col) & 1ull)) {
                gb |= (1ull << col);
                gw0 += wg[lane*33 + col];
                if (hi) gw1 += wg[(32 + lane)*33 + col];
            }
        }
    }
}

// =============================================================================
extern "C" void kernel_launch(void* const* d_in, const int* in_sizes, int n_in,
                              void* d_out, int out_size)
{
    const int*   ids  = (const int*)  d_in[0];
    const float* emb  = (const float*)d_in[1];
    const float* wihf = (const float*)d_in[2];
    const float* whhf = (const float*)d_in[3];
    const float* bihf = (const float*)d_in[4];
    const float* bhhf = (const float*)d_in[5];
    const float* wihb = (const float*)d_in[6];
    const float* whhb = (const float*)d_in[7];
    const float* bihb = (const float*)d_in[8];
    const float* bhhb = (const float*)d_in[9];
    const float* ew   = (const float*)d_in[10];
    const float* eb   = (const float*)d_in[11];
    const float* aw   = (const float*)d_in[12];
    const float* ab   = (const float*)d_in[13];
    float* out = (float*)d_out;

    gemm_xw_kernel<<<dim3(8,32), 256>>>(ids, emb, wihf, wihb, bihf, bhhf, bihb, bhhb);
    lstm_kernel<<<128, 256>>>(whhf, whhb);
    head_kernel<<<64, 256>>>(ew, eb, aw, ab, out);
    scan_kernel<<<1024, 128>>>(aw, out);
}

// round 3
// speedup vs baseline: 1.5109x; 1.5109x over previous
#include <cuda_runtime.h>
#include <cstdint>
#include <math.h>

#define B_ 32
#define L_ 128
#define D_ 300
#define H_ 128
#define E_ 34
#define A_ 36
#define M_ (B_*L_)          // 4096
#define NXW 1024
#define ARG_OFF (B_*L_*E_)  // 139264

// ------------------------- scratch (no allocs allowed) -----------------------
__device__ float g_xw[M_*NXW];       // x@W_ih^T + b_ih + b_hh, both dirs
__device__ float g_hidden[M_*256];   // [h_f | h_b]
__device__ float g_base[M_*A_];      // hidden@argW_h^T + arg_b
__device__ float g_trig[M_*A_];      // hidden@argW_t^T
__device__ int   g_evp[M_];          // argmax(event_logits)

// ------------------------- helpers ------------------------------------------
__device__ __forceinline__ unsigned long long pack2(float lo, float hi){
    unsigned long long r;
    asm("mov.b64 %0, {%1, %2};" : "=l"(r) : "f"(lo), "f"(hi));
    return r;
}
__device__ __forceinline__ void unpack2(unsigned long long v, float& lo, float& hi){
    asm("mov.b64 {%0, %1}, %2;" : "=f"(lo), "=f"(hi) : "l"(v));
}
__device__ __forceinline__ unsigned long long fma2(unsigned long long a,
                                                   unsigned long long b,
                                                   unsigned long long c){
    unsigned long long d;
    asm("fma.rn.f32x2 %0, %1, %2, %3;" : "=l"(d) : "l"(a), "l"(b), "l"(c));
    return d;
}
__device__ __forceinline__ uint32_t smem_u32(const void* p){
    return (uint32_t)__cvta_generic_to_shared(p);
}
__device__ __forceinline__ uint32_t mapa_u32(uint32_t a, uint32_t r){
    uint32_t d;
    asm("mapa.shared::cluster.u32 %0, %1, %2;" : "=r"(d) : "r"(a), "r"(r));
    return d;
}
__device__ __forceinline__ unsigned redux_max_u32(unsigned v){
    unsigned r; asm("redux.sync.max.u32 %0, %1, 0xffffffff;" : "=r"(r) : "r"(v)); return r;
}
__device__ __forceinline__ unsigned redux_min_u32(unsigned v){
    unsigned r; asm("redux.sync.min.u32 %0, %1, 0xffffffff;" : "=r"(r) : "r"(v)); return r;
}
#define CLUSTER_SYNC_() do { \
    asm volatile("barrier.cluster.arrive.aligned;" ::: "memory"); \
    asm volatile("barrier.cluster.wait.aligned;"   ::: "memory"); \
} while(0)
#define CLUSTER_ARRIVE_() asm volatile("barrier.cluster.arrive.aligned;" ::: "memory")
#define CLUSTER_WAIT_()   asm volatile("barrier.cluster.wait.aligned;"   ::: "memory")

// =============================================================================
// Kernel 1: xW = gather(emb, ids) @ [w_ih_f^T | w_ih_b^T] + (b_ih + b_hh)
// M=4096, N=1024, K=300.  128x128 tiles, 256 threads, 8x8 micro, f32x2 FMA.
// =============================================================================
__global__ __launch_bounds__(256) void gemm_xw_kernel(
    const int* __restrict__ ids, const float* __restrict__ emb,
    const float* __restrict__ wf, const float* __restrict__ wb,
    const float* __restrict__ bihf, const float* __restrict__ bhhf,
    const float* __restrict__ bihb, const float* __restrict__ bhhb)
{
    __shared__ float As[8][132];
    __shared__ float Bs[8][132];
    __shared__ int ids_s[128];

    int t  = threadIdx.x;
    int m0 = blockIdx.y * 128;
    int n0 = blockIdx.x * 128;

    const float* w;
    const float *b1, *b2;
    if (n0 < 512) { w = wf + (size_t)n0 * D_;        b1 = bihf + n0;        b2 = bhhf + n0; }
    else          { w = wb + (size_t)(n0-512) * D_;  b1 = bihb + (n0-512);  b2 = bhhb + (n0-512); }

    if (t < 128) ids_s[t] = ids[m0 + t];
    __syncthreads();

    int tx = t & 15, ty = t >> 4;
    unsigned long long acc[8][4];
#pragma unroll
    for (int r = 0; r < 8; r++)
#pragma unroll
        for (int p = 0; p < 4; p++) acc[r][p] = 0ull;

    int ai = t & 127, akk = (t >> 7) * 4;   // A loader: (row ai, kk akk..akk+3)
    int bj = t >> 3,  bkk = t & 7;          // B loader: (rows bj+32c, kk bkk)

    for (int k0 = 0; k0 < D_; k0 += 8) {
        const float* arow = emb + (size_t)ids_s[ai] * D_;
#pragma unroll
        for (int c = 0; c < 4; c++) {
            int kk = akk + c;
            As[kk][ai] = (k0 + kk < D_) ? arow[k0 + kk] : 0.f;
        }
#pragma unroll
        for (int c = 0; c < 4; c++) {
            int j = bj + 32 * c;
            Bs[bkk][j] = (k0 + bkk < D_) ? w[(size_t)j * D_ + k0 + bkk] : 0.f;
        }
        __syncthreads();
#pragma unroll
        for (int kk = 0; kk < 8; kk++) {
            float a_[8];
#pragma unroll
            for (int r = 0; r < 8; r++) a_[r] = As[kk][ty*8 + r];
            unsigned long long b2v[4];
            const float2* bp = (const float2*)&Bs[kk][tx*8];
#pragma unroll
            for (int p = 0; p < 4; p++) { float2 v = bp[p]; b2v[p] = pack2(v.x, v.y); }
#pragma unroll
            for (int r = 0; r < 8; r++) {
                unsigned long long a2 = pack2(a_[r], a_[r]);
#pragma unroll
                for (int p = 0; p < 4; p++) acc[r][p] = fma2(a2, b2v[p], acc[r][p]);
            }
        }
        __syncthreads();
    }

#pragma unroll
    for (int r = 0; r < 8; r++) {
        int m = m0 + ty*8 + r;
#pragma unroll
        for (int p = 0; p < 4; p++) {
            float lo, hi; unpack2(acc[r][p], lo, hi);
            int nlo = tx*8 + 2*p;
            g_xw[(size_t)m * NXW + n0 + nlo]     = lo + b1[nlo]   + b2[nlo];
            g_xw[(size_t)m * NXW + n0 + nlo + 1] = hi + b1[nlo+1] + b2[nlo+1];
        }
    }
}

// =============================================================================
// Kernel 2: BiLSTM recurrence (R1 cluster.sync structure, f32x2 dot, split
// arrive/wait so g_xw L2 latency overlaps barrier drain).
// 16 clusters of 8 CTAs: cluster = (dir, batch-group of 4). CTA = 16 hidden
// units (64 gate rows). W_hh slice in registers as packed f32x2 (16 x ull).
// =============================================================================
__global__ void __cluster_dims__(8,1,1) __launch_bounds__(256,1)
lstm_kernel(const float* __restrict__ whf, const float* __restrict__ whb)
{
    __shared__ __align__(16) float h_sm[2][4][132];   // [phase][batch][128+pad]
    __shared__ float z_sm[4][64];

    int bx   = blockIdx.x;
    int cid  = bx >> 3, rank = bx & 7;
    int dir  = cid & 1,  bg  = cid >> 1;      // batches bg*4 .. bg*4+3
    int u0   = rank * 16;

    int t = threadIdx.x, lane = t & 31, warp = t >> 5;
    int rl = lane & 7, kq = lane >> 3;
    int row  = warp*8 + rl;                   // 0..63 local gate row
    int gate = row >> 4, uu = row & 15;
    int grow = gate*H_ + u0 + uu;             // global gate row 0..511

    const float* whh = dir ? whb : whf;
    unsigned long long w2[16];                // 32 weights packed as f32x2
    {
        const float4* wrow = (const float4*)(whh + (size_t)grow*H_ + kq*32);
#pragma unroll
        for (int i = 0; i < 8; i++) {
            float4 wv = wrow[i];
            w2[2*i]   = pack2(wv.x, wv.y);
            w2[2*i+1] = pack2(wv.z, wv.w);
        }
    }

    for (int idx = t; idx < 2*4*132; idx += 256) (&h_sm[0][0][0])[idx] = 0.f;

    int ub = t >> 4, uuu = t & 15;            // updater role (t < 64)
    float c_reg = 0.f;

    CLUSTER_SYNC_();                          // zeroed h visible cluster-wide

    int xw_col = dir*512 + grow;

    for (int s = 0; s < L_; s++) {
        int ph = s & 1;
        int tc = dir ? (L_-1-s) : s;

        // xw loads are barrier-independent: issue before the wait.
        float xwv0=0.f, xwv1=0.f, xwv2=0.f, xwv3=0.f;
        if (kq == 0) {
            size_t base = ((size_t)(bg*4)*L_ + tc) * NXW + xw_col;
            xwv0 = g_xw[base];
            xwv1 = g_xw[base + (size_t)L_*NXW];
            xwv2 = g_xw[base + (size_t)2*L_*NXW];
            xwv3 = g_xw[base + (size_t)3*L_*NXW];
        }

        if (s > 0) CLUSTER_WAIT_();           // closes arrive of step s-1

        float a[4];
#pragma unroll
        for (int b = 0; b < 4; b++) {
            unsigned long long acc = 0ull;
            const float4* hp = (const float4*)&h_sm[ph][b][kq*32];
#pragma unroll
            for (int i = 0; i < 8; i++) {
                float4 hv = hp[i];
                acc = fma2(w2[2*i],   pack2(hv.x, hv.y), acc);
                acc = fma2(w2[2*i+1], pack2(hv.z, hv.w), acc);
            }
            float lo, hi; unpack2(acc, lo, hi);
            a[b] = lo + hi;
        }
#pragma unroll
        for (int b = 0; b < 4; b++) {
            a[b] += __shfl_xor_sync(~0u, a[b], 8);
            a[b] += __shfl_xor_sync(~0u, a[b], 16);
        }

        if (kq == 0) {
            z_sm[0][row] = a[0] + xwv0;
            z_sm[1][row] = a[1] + xwv1;
            z_sm[2][row] = a[2] + xwv2;
            z_sm[3][row] = a[3] + xwv3;
        }
        __syncthreads();

        if (t < 64) {
            float zi = z_sm[ub][uuu],      zf = z_sm[ub][16 + uuu];
            float zg = z_sm[ub][32 + uuu], zo = z_sm[ub][48 + uuu];
            float ig = 1.f / (1.f + expf(-zi));
            float fg = 1.f / (1.f + expf(-zf));
            float gg = tanhf(zg);
            float og = 1.f / (1.f + expf(-zo));
            c_reg = fg * c_reg + ig * gg;
            float h = og * tanhf(c_reg);

            int k = u0 + uuu;
            uint32_t loc = smem_u32(&h_sm[ph ^ 1][ub][k]);
#pragma unroll
            for (int r = 0; r < 8; r++) {
                uint32_t ra = mapa_u32(loc, (uint32_t)r);
                asm volatile("st.shared::cluster.f32 [%0], %1;" :: "r"(ra), "f"(h));
            }
            g_hidden[((size_t)((bg*4 + ub)*L_ + tc)) * 256 + dir*H_ + k] = h;
        }

        CLUSTER_ARRIVE_();   // release: orders this thread's DSMEM stores
    }
    CLUSTER_WAIT_();         // close final arrive; drains in-flight stores
}

// =============================================================================
// Kernel 3: fused head GEMM + event argmax.
// hidden[4096,256] @ W2^T, W2 rows = [event_w(34) | argW[:, :256](36) |
// argW[:,256:512](36)] -> 106 cols. Epilogue: argmax over 34 -> g_evp.
// =============================================================================
__global__ __launch_bounds__(256) void head_kernel(
    const float* __restrict__ ew, const float* __restrict__ eb,
    const float* __restrict__ aw, const float* __restrict__ ab,
    float* __restrict__ out)
{
    __shared__ float hsm[64][65];
    __shared__ float wsm[64][108];
    __shared__ float ev_sm[64][36];

    int t  = threadIdx.x;
    int m0 = blockIdx.x * 64;
    int ml = t >> 2, ng = t & 3;

    float acc[27];
#pragma unroll
    for (int c = 0; c < 27; c++) acc[c] = 0.f;

    for (int k0 = 0; k0 < 256; k0 += 64) {
        for (int idx = t; idx < 64*64; idx += 256) {
            int r = idx >> 6, c = idx & 63;
            hsm[r][c] = g_hidden[(size_t)(m0 + r)*256 + k0 + c];
        }
        for (int idx = t; idx < 64*108; idx += 256) {
            int kk = idx / 108, n = idx % 108;
            int k  = k0 + kk;
            float v = 0.f;
            if      (n < 34)  v = ew[(size_t)n*256 + k];
            else if (n < 70)  v = aw[(size_t)(n-34)*545 + k];
            else if (n < 106) v = aw[(size_t)(n-70)*545 + 256 + k];
            wsm[kk][n] = v;
        }
        __syncthreads();
#pragma unroll 8
        for (int kk = 0; kk < 64; kk++) {
            float hv = hsm[ml][kk];
#pragma unroll
            for (int c = 0; c < 27; c++) acc[c] += hv * wsm[kk][ng*27 + c];
        }
        __syncthreads();
    }

    int m = m0 + ml;
#pragma unroll
    for (int c = 0; c < 27; c++) {
        int n = ng*27 + c;
        if (n < 34) {
            float v = acc[c] + eb[n];
            out[(size_t)m*E_ + n] = v;
            ev_sm[ml][n] = v;
        }
        else if (n < 70)  g_base[(size_t)m*A_ + (n-34)] = acc[c] + ab[n-34];
        else if (n < 106) g_trig[(size_t)m*A_ + (n-70)] = acc[c];
    }
    __syncthreads();

    if (t < 64) {
        float bv = ev_sm[t][0]; int bi = 0;
#pragma unroll
        for (int e = 1; e < E_; e++) {
            float v = ev_sm[t][e];
            if (v > bv) { bv = v; bi = e; }
        }
        g_evp[m0 + t] = bi;
    }
}

// =============================================================================
// Kernel 4: scan. One warp per (b, l); g[b,l] is an independent 33-bit state.
// arg_logit[i] = base[b,l] + trig[b,i] + gW (incrementally maintained).
// Argmax via 2x redux.sync (ordered-u32 map); trig prefetched one step ahead.
// =============================================================================
__global__ __launch_bounds__(128) void scan_kernel(
    const float* __restrict__ aw, float* __restrict__ out)
{
    __shared__ float wg[36*33];   // arg_w[:, 512:545]
    int t = threadIdx.x;
    for (int idx = t; idx < 36*33; idx += 128) {
        int a = idx / 33, c = idx % 33;
        wg[idx] = aw[(size_t)a*545 + 512 + c];
    }
    __syncthreads();

    int gw_id = blockIdx.x * 4 + (t >> 5);
    int lane  = t & 31;
    int b = gw_id >> 7, l = gw_id & 127;
    size_t bl = (size_t)(b*L_ + l);

    // byte-pack this batch's 128 ev_preds: lane j holds evp[b, 4j..4j+3]
    const int* evb = g_evp + b*L_ + lane*4;
    int ep4 = evb[0] | (evb[1] << 8) | (evb[2] << 16) | (evb[3] << 24);

    bool hi = lane < 4;
    float base0 = g_base[bl*A_ + lane];
    float base1 = hi ? g_base[bl*A_ + 32 + lane] : -3.4e38f;
    float gw0 = 0.f, gw1 = 0.f;
    unsigned long long gb = 0ull;
    float* oarg = out + ARG_OFF;

    const float* trg = g_trig + (size_t)b*L_*A_;
    float t0 = trg[lane];
    float t1 = hi ? trg[32 + lane] : 0.f;

    for (int i = 0; i < L_; i++) {
        // prefetch next step's trig before the serial tail
        float t0n = 0.f, t1n = 0.f;
        if (i + 1 < L_) {
            t0n = trg[(i+1)*A_ + lane];
            if (hi) t1n = trg[(i+1)*A_ + 32 + lane];
        }

        float v0 = base0 + t0 + gw0;
        float v1 = hi ? (base1 + t1 + gw1) : -3.4e38f;

        size_t ob = ((size_t)(b*L_ + i)*L_ + l) * A_;
        oarg[ob + lane] = v0;
        if (hi) oarg[ob + 32 + lane] = v1;

        // first-max argmax over 36 values via 2x redux
        float bv = v0; int bidx = lane;
        if (hi && v1 > bv) { bv = v1; bidx = lane + 32; }
        unsigned fu = __float_as_uint(bv);
        unsigned mu = (fu & 0x80000000u) ? ~fu : (fu | 0x80000000u);
        unsigned mx = redux_max_u32(mu);
        unsigned cand = (mu == mx) ? (unsigned)bidx : 0xffffffffu;
        unsigned widx = redux_min_u32(cand);

        int ep = (__shfl_sync(0xffffffffu, ep4, i >> 2) >> ((i & 3) * 8)) & 0xff;
        if (ep > 0 && widx > 0) {
            int col = ep - 1;
            if (!((gb >> col) & 1ull)) {
                gb |= (1ull << col);
                gw0 += wg[lane*33 + col];
                if (hi) gw1 += wg[(32 + lane)*33 + col];
            }
        }
        t0 = t0n; t1 = t1n;
    }
}

// =============================================================================
extern "C" void kernel_launch(void* const* d_in, const int* in_sizes, int n_in,
                              void* d_out, int out_size)
{
    const int*   ids  = (const int*)  d_in[0];
    const float* emb  = (const float*)d_in[1];
    const float* wihf = (const float*)d_in[2];
    const float* whhf = (const float*)d_in[3];
    const float* bihf = (const float*)d_in[4];
    const float* bhhf = (const float*)d_in[5];
    const float* wihb = (const float*)d_in[6];
    const float* whhb = (const float*)d_in[7];
    const float* bihb = (const float*)d_in[8];
    const float* bhhb = (const float*)d_in[9];
    const float* ew   = (const float*)d_in[10];
    const float* eb   = (const float*)d_in[11];
    const float* aw   = (const float*)d_in[12];
    const float* ab   = (const float*)d_in[13];
    float* out = (float*)d_out;

    gemm_xw_kernel<<<dim3(8,32), 256>>>(ids, emb, wihf, wihb, bihf, bhhf, bihb, bhhb);
    lstm_kernel<<<128, 256>>>(whhf, whhb);
    head_kernel<<<64, 256>>>(ew, eb, aw, ab, out);
    scan_kernel<<<1024, 128>>>(aw, out);
}

// round 4
// speedup vs baseline: 2.0432x; 1.3524x over previous
#include <cuda_runtime.h>
#include <cstdint>
#include <math.h>

#define B_ 32
#define L_ 128
#define D_ 300
#define H_ 128
#define E_ 34
#define A_ 36
#define M_ (B_*L_)          // 4096
#define NXW 1024
#define ARG_OFF (B_*L_*E_)  // 139264

// ------------------------- scratch (no allocs allowed) -----------------------
__device__ float g_xw[M_*NXW];       // x@W_ih^T + b_ih + b_hh, both dirs
__device__ float g_hidden[M_*256];   // [h_f | h_b]
__device__ float g_base[M_*A_];      // hidden@argW_h^T + arg_b
__device__ float g_trig[M_*A_];      // hidden@argW_t^T
__device__ int   g_evp[M_];          // argmax(event_logits)

// ------------------------- helpers ------------------------------------------
__device__ __forceinline__ unsigned long long pack2(float lo, float hi){
    unsigned long long r;
    asm("mov.b64 %0, {%1, %2};" : "=l"(r) : "f"(lo), "f"(hi));
    return r;
}
__device__ __forceinline__ void unpack2(unsigned long long v, float& lo, float& hi){
    asm("mov.b64 {%0, %1}, %2;" : "=f"(lo), "=f"(hi) : "l"(v));
}
__device__ __forceinline__ unsigned long long fma2(unsigned long long a,
                                                   unsigned long long b,
                                                   unsigned long long c){
    unsigned long long d;
    asm("fma.rn.f32x2 %0, %1, %2, %3;" : "=l"(d) : "l"(a), "l"(b), "l"(c));
    return d;
}
__device__ __forceinline__ uint32_t smem_u32(const void* p){
    return (uint32_t)__cvta_generic_to_shared(p);
}
__device__ __forceinline__ uint32_t mapa_u32(uint32_t a, uint32_t r){
    uint32_t d;
    asm("mapa.shared::cluster.u32 %0, %1, %2;" : "=r"(d) : "r"(a), "r"(r));
    return d;
}
__device__ __forceinline__ unsigned redux_max_u32(unsigned v){
    unsigned r; asm("redux.sync.max.u32 %0, %1, 0xffffffff;" : "=r"(r) : "r"(v)); return r;
}
__device__ __forceinline__ unsigned redux_min_u32(unsigned v){
    unsigned r; asm("redux.sync.min.u32 %0, %1, 0xffffffff;" : "=r"(r) : "r"(v)); return r;
}
#define CLUSTER_SYNC_() do { \
    asm volatile("barrier.cluster.arrive.aligned;" ::: "memory"); \
    asm volatile("barrier.cluster.wait.aligned;"   ::: "memory"); \
} while(0)

// =============================================================================
// Kernel 1: xW = gather(emb, ids) @ [w_ih_f^T | w_ih_b^T] + (b_ih + b_hh)
// M=4096, N=1024, K=300.  128x128 tiles, 256 threads, 8x8 micro, f32x2 FMA.
// =============================================================================
__global__ __launch_bounds__(256) void gemm_xw_kernel(
    const int* __restrict__ ids, const float* __restrict__ emb,
    const float* __restrict__ wf, const float* __restrict__ wb,
    const float* __restrict__ bihf, const float* __restrict__ bhhf,
    const float* __restrict__ bihb, const float* __restrict__ bhhb)
{
    __shared__ float As[8][132];
    __shared__ float Bs[8][132];
    __shared__ int ids_s[128];

    int t  = threadIdx.x;
    int m0 = blockIdx.y * 128;
    int n0 = blockIdx.x * 128;

    const float* w;
    const float *b1, *b2;
    if (n0 < 512) { w = wf + (size_t)n0 * D_;        b1 = bihf + n0;        b2 = bhhf + n0; }
    else          { w = wb + (size_t)(n0-512) * D_;  b1 = bihb + (n0-512);  b2 = bhhb + (n0-512); }

    if (t < 128) ids_s[t] = ids[m0 + t];
    __syncthreads();

    int tx = t & 15, ty = t >> 4;
    unsigned long long acc[8][4];
#pragma unroll
    for (int r = 0; r < 8; r++)
#pragma unroll
        for (int p = 0; p < 4; p++) acc[r][p] = 0ull;

    int ai = t & 127, akk = (t >> 7) * 4;   // A loader: (row ai, kk akk..akk+3)
    int bj = t >> 3,  bkk = t & 7;          // B loader: (rows bj+32c, kk bkk)

    for (int k0 = 0; k0 < D_; k0 += 8) {
        const float* arow = emb + (size_t)ids_s[ai] * D_;
#pragma unroll
        for (int c = 0; c < 4; c++) {
            int kk = akk + c;
            As[kk][ai] = (k0 + kk < D_) ? arow[k0 + kk] : 0.f;
        }
#pragma unroll
        for (int c = 0; c < 4; c++) {
            int j = bj + 32 * c;
            Bs[bkk][j] = (k0 + bkk < D_) ? w[(size_t)j * D_ + k0 + bkk] : 0.f;
        }
        __syncthreads();
#pragma unroll
        for (int kk = 0; kk < 8; kk++) {
            float a_[8];
#pragma unroll
            for (int r = 0; r < 8; r++) a_[r] = As[kk][ty*8 + r];
            unsigned long long b2v[4];
            const float2* bp = (const float2*)&Bs[kk][tx*8];
#pragma unroll
            for (int p = 0; p < 4; p++) { float2 v = bp[p]; b2v[p] = pack2(v.x, v.y); }
#pragma unroll
            for (int r = 0; r < 8; r++) {
                unsigned long long a2 = pack2(a_[r], a_[r]);
#pragma unroll
                for (int p = 0; p < 4; p++) acc[r][p] = fma2(a2, b2v[p], acc[r][p]);
            }
        }
        __syncthreads();
    }

#pragma unroll
    for (int r = 0; r < 8; r++) {
        int m = m0 + ty*8 + r;
#pragma unroll
        for (int p = 0; p < 4; p++) {
            float lo, hi; unpack2(acc[r][p], lo, hi);
            int nlo = tx*8 + 2*p;
            g_xw[(size_t)m * NXW + n0 + nlo]     = lo + b1[nlo]   + b2[nlo];
            g_xw[(size_t)m * NXW + n0 + nlo + 1] = hi + b1[nlo+1] + b2[nlo+1];
        }
    }
}

// =============================================================================
// Kernel 2: BiLSTM recurrence (R1 structure: cluster.sync at loop end).
// 16 clusters of 8 CTAs: cluster = (dir, batch-group of 4). CTA = 16 hidden
// units (64 gate rows). W_hh slice as 32 scalar floats in registers.
// ONLY change vs R1: h read via float4 (LDS.128), scalar FFMA.
// =============================================================================
__global__ void __cluster_dims__(8,1,1) __launch_bounds__(256,1)
lstm_kernel(const float* __restrict__ whf, const float* __restrict__ whb)
{
    __shared__ __align__(16) float h_sm[2][4*144];   // [phase][b*144 + kq*36 + j]
    __shared__ float z_sm[4][64];

    int bx   = blockIdx.x;
    int cid  = bx >> 3, rank = bx & 7;
    int dir  = cid & 1,  bg  = cid >> 1;      // batches bg*4 .. bg*4+3
    int u0   = rank * 16;

    int t = threadIdx.x, lane = t & 31, warp = t >> 5;
    int rl = lane & 7, kq = lane >> 3;
    int row  = warp*8 + rl;                   // 0..63 local gate row
    int gate = row >> 4, uu = row & 15;
    int grow = gate*H_ + u0 + uu;             // global gate row 0..511

    const float* whh = dir ? whb : whf;
    float w_reg[32];
#pragma unroll
    for (int j = 0; j < 32; j++) w_reg[j] = whh[(size_t)grow*H_ + kq*32 + j];

    for (int idx = t; idx < 2*576; idx += 256) ((float*)h_sm)[idx] = 0.f;

    int ub = t >> 4, uuu = t & 15;            // updater role (t < 64)
    float c_reg = 0.f;

    CLUSTER_SYNC_();

    int phase  = 0;
    int xw_col = dir*512 + grow;

    for (int s = 0; s < L_; s++) {
        int tc = dir ? (L_-1-s) : s;

        float xwv0=0.f, xwv1=0.f, xwv2=0.f, xwv3=0.f;
        if (kq == 0) {
            size_t base = ((size_t)(bg*4)*L_ + tc) * NXW + xw_col;
            xwv0 = g_xw[base];
            xwv1 = g_xw[base + (size_t)L_*NXW];
            xwv2 = g_xw[base + (size_t)2*L_*NXW];
            xwv3 = g_xw[base + (size_t)3*L_*NXW];
        }

        const float4* h0 = (const float4*)&h_sm[phase][kq*36];
        const float4* h1 = (const float4*)&h_sm[phase][144 + kq*36];
        const float4* h2 = (const float4*)&h_sm[phase][288 + kq*36];
        const float4* h3 = (const float4*)&h_sm[phase][432 + kq*36];
        float a0=0.f, a1=0.f, a2=0.f, a3=0.f;
#pragma unroll
        for (int i = 0; i < 8; i++) {
            float4 v0 = h0[i], v1 = h1[i], v2 = h2[i], v3 = h3[i];
            float w0 = w_reg[4*i], w1 = w_reg[4*i+1], w2 = w_reg[4*i+2], w3 = w_reg[4*i+3];
            a0 += w0*v0.x; a0 += w1*v0.y; a0 += w2*v0.z; a0 += w3*v0.w;
            a1 += w0*v1.x; a1 += w1*v1.y; a1 += w2*v1.z; a1 += w3*v1.w;
            a2 += w0*v2.x; a2 += w1*v2.y; a2 += w2*v2.z; a2 += w3*v2.w;
            a3 += w0*v3.x; a3 += w1*v3.y; a3 += w2*v3.z; a3 += w3*v3.w;
        }
        a0 += __shfl_xor_sync(~0u, a0, 8);  a0 += __shfl_xor_sync(~0u, a0, 16);
        a1 += __shfl_xor_sync(~0u, a1, 8);  a1 += __shfl_xor_sync(~0u, a1, 16);
        a2 += __shfl_xor_sync(~0u, a2, 8);  a2 += __shfl_xor_sync(~0u, a2, 16);
        a3 += __shfl_xor_sync(~0u, a3, 8);  a3 += __shfl_xor_sync(~0u, a3, 16);

        if (kq == 0) {
            z_sm[0][row] = a0 + xwv0;
            z_sm[1][row] = a1 + xwv1;
            z_sm[2][row] = a2 + xwv2;
            z_sm[3][row] = a3 + xwv3;
        }
        __syncthreads();

        if (t < 64) {
            float zi = z_sm[ub][uuu],      zf = z_sm[ub][16 + uuu];
            float zg = z_sm[ub][32 + uuu], zo = z_sm[ub][48 + uuu];
            float ig = 1.f / (1.f + expf(-zi));
            float fg = 1.f / (1.f + expf(-zf));
            float gg = tanhf(zg);
            float og = 1.f / (1.f + expf(-zo));
            c_reg = fg * c_reg + ig * gg;
            float h = og * tanhf(c_reg);

            int k = u0 + uuu;
            uint32_t loc = smem_u32(&h_sm[phase ^ 1][ub*144 + (k>>5)*36 + (k&31)]);
#pragma unroll
            for (int r = 0; r < 8; r++) {
                uint32_t ra = mapa_u32(loc, (uint32_t)r);
                asm volatile("st.shared::cluster.f32 [%0], %1;" :: "r"(ra), "f"(h));
            }
            g_hidden[((size_t)((bg*4 + ub)*L_ + tc)) * 256 + dir*H_ + k] = h;
        }

        CLUSTER_SYNC_();
        phase ^= 1;
    }
}

// =============================================================================
// Kernel 3: fused head GEMM + event argmax.
// hidden[4096,256] @ W2^T, W2 rows = [event_w(34) | argW[:, :256](36) |
// argW[:,256:512](36)] -> 106 cols. Epilogue: argmax over 34 -> g_evp.
// =============================================================================
__global__ __launch_bounds__(256) void head_kernel(
    const float* __restrict__ ew, const float* __restrict__ eb,
    const float* __restrict__ aw, const float* __restrict__ ab,
    float* __restrict__ out)
{
    __shared__ float hsm[64][65];
    __shared__ float wsm[64][108];
    __shared__ float ev_sm[64][36];

    int t  = threadIdx.x;
    int m0 = blockIdx.x * 64;
    int ml = t >> 2, ng = t & 3;

    float acc[27];
#pragma unroll
    for (int c = 0; c < 27; c++) acc[c] = 0.f;

    for (int k0 = 0; k0 < 256; k0 += 64) {
        for (int idx = t; idx < 64*64; idx += 256) {
            int r = idx >> 6, c = idx & 63;
            hsm[r][c] = g_hidden[(size_t)(m0 + r)*256 + k0 + c];
        }
        for (int idx = t; idx < 64*108; idx += 256) {
            int kk = idx / 108, n = idx % 108;
            int k  = k0 + kk;
            float v = 0.f;
            if      (n < 34)  v = ew[(size_t)n*256 + k];
            else if (n < 70)  v = aw[(size_t)(n-34)*545 + k];
            else if (n < 106) v = aw[(size_t)(n-70)*545 + 256 + k];
            wsm[kk][n] = v;
        }
        __syncthreads();
#pragma unroll 8
        for (int kk = 0; kk < 64; kk++) {
            float hv = hsm[ml][kk];
#pragma unroll
            for (int c = 0; c < 27; c++) acc[c] += hv * wsm[kk][ng*27 + c];
        }
        __syncthreads();
    }

    int m = m0 + ml;
#pragma unroll
    for (int c = 0; c < 27; c++) {
        int n = ng*27 + c;
        if (n < 34) {
            float v = acc[c] + eb[n];
            out[(size_t)m*E_ + n] = v;
            ev_sm[ml][n] = v;
        }
        else if (n < 70)  g_base[(size_t)m*A_ + (n-34)] = acc[c] + ab[n-34];
        else if (n < 106) g_trig[(size_t)m*A_ + (n-70)] = acc[c];
    }
    __syncthreads();

    if (t < 64) {
        float bv = ev_sm[t][0]; int bi = 0;
#pragma unroll
        for (int e = 1; e < E_; e++) {
            float v = ev_sm[t][e];
            if (v > bv) { bv = v; bi = e; }
        }
        g_evp[m0 + t] = bi;
    }
}

// =============================================================================
// Kernel 4: scan. One warp per (b, pair of l); each l's g is an independent
// 33-bit state. arg_logit[i] = base[b,l] + trig[b,i] + gW (incremental).
// trig/ev_pred shared across the 2 l's; 2 interleaved redux-argmax chains.
// =============================================================================
__global__ __launch_bounds__(128) void scan_kernel(
    const float* __restrict__ aw, float* __restrict__ out)
{
    __shared__ float wg[36*33];   // arg_w[:, 512:545]
    int t = threadIdx.x;
    for (int idx = t; idx < 36*33; idx += 128) {
        int a = idx / 33, c = idx % 33;
        wg[idx] = aw[(size_t)a*545 + 512 + c];
    }
    __syncthreads();

    int gw_id = blockIdx.x * 4 + (t >> 5);   // 0..2047
    int lane  = t & 31;
    int b  = gw_id >> 6;
    int l0 = (gw_id & 63) * 2;
    int l1 = l0 + 1;

    // byte-pack this batch's 128 ev_preds: lane j holds evp[b, 4j..4j+3]
    const int* evb = g_evp + b*L_ + lane*4;
    int ep4 = evb[0] | (evb[1] << 8) | (evb[2] << 16) | (evb[3] << 24);

    bool hi = lane < 4;
    size_t blA0 = (size_t)(b*L_ + l0) * A_;
    size_t blA1 = (size_t)(b*L_ + l1) * A_;
    float baseA0 = g_base[blA0 + lane];
    float baseA1 = hi ? g_base[blA0 + 32 + lane] : -3.4e38f;
    float baseB0 = g_base[blA1 + lane];
    float baseB1 = hi ? g_base[blA1 + 32 + lane] : -3.4e38f;
    float gwA0 = 0.f, gwA1 = 0.f, gwB0 = 0.f, gwB1 = 0.f;
    unsigned long long gbA = 0ull, gbB = 0ull;
    float* oarg = out + ARG_OFF;

    const float* trg = g_trig + (size_t)b*L_*A_;
    float t0 = trg[lane];
    float t1 = hi ? trg[32 + lane] : 0.f;

    for (int i = 0; i < L_; i++) {
        // prefetch next step's trig before the serial tail
        float t0n = 0.f, t1n = 0.f;
        if (i + 1 < L_) {
            t0n = trg[(i+1)*A_ + lane];
            if (hi) t1n = trg[(i+1)*A_ + 32 + lane];
        }

        float vA0 = baseA0 + t0 + gwA0;
        float vA1 = hi ? (baseA1 + t1 + gwA1) : -3.4e38f;
        float vB0 = baseB0 + t0 + gwB0;
        float vB1 = hi ? (baseB1 + t1 + gwB1) : -3.4e38f;

        size_t ob = ((size_t)(b*L_ + i)*L_ + l0) * A_;
        oarg[ob + lane] = vA0;
        if (hi) oarg[ob + 32 + lane] = vA1;
        oarg[ob + A_ + lane] = vB0;
        if (hi) oarg[ob + A_ + 32 + lane] = vB1;

        // two interleaved first-max argmax chains (ordered-u32 map + 2 redux)
        float bvA = vA0; int biA = lane;
        if (hi && vA1 > bvA) { bvA = vA1; biA = lane + 32; }
        float bvB = vB0; int biB = lane;
        if (hi && vB1 > bvB) { bvB = vB1; biB = lane + 32; }

        unsigned fuA = __float_as_uint(bvA);
        unsigned muA = (fuA & 0x80000000u) ? ~fuA : (fuA | 0x80000000u);
        unsigned fuB = __float_as_uint(bvB);
        unsigned muB = (fuB & 0x80000000u) ? ~fuB : (fuB | 0x80000000u);
        unsigned mxA = redux_max_u32(muA);
        unsigned mxB = redux_max_u32(muB);
        unsigned cA = (muA == mxA) ? (unsigned)biA : 0xffffffffu;
        unsigned cB = (muB == mxB) ? (unsigned)biB : 0xffffffffu;
        unsigned wA = redux_min_u32(cA);
        unsigned wB = redux_min_u32(cB);

        int ep = (__shfl_sync(0xffffffffu, ep4, i >> 2) >> ((i & 3) * 8)) & 0xff;
        if (ep > 0) {
            int col = ep - 1;
            if (wA > 0 && !((gbA >> col) & 1ull)) {
                gbA |= (1ull << col);
                gwA0 += wg[lane*33 + col];
                if (hi) gwA1 += wg[(32 + lane)*33 + col];
            }
            if (wB > 0 && !((gbB >> col) & 1ull)) {
                gbB |= (1ull << col);
                gwB0 += wg[lane*33 + col];
                if (hi) gwB1 += wg[(32 + lane)*33 + col];
            }
        }
        t0 = t0n; t1 = t1n;
    }
}

// =============================================================================
extern "C" void kernel_launch(void* const* d_in, const int* in_sizes, int n_in,
                              void* d_out, int out_size)
{
    const int*   ids  = (const int*)  d_in[0];
    const float* emb  = (const float*)d_in[1];
    const float* wihf = (const float*)d_in[2];
    const float* whhf = (const float*)d_in[3];
    const float* bihf = (const float*)d_in[4];
    const float* bhhf = (const float*)d_in[5];
    const float* wihb = (const float*)d_in[6];
    const float* whhb = (const float*)d_in[7];
    const float* bihb = (const float*)d_in[8];
    const float* bhhb = (const float*)d_in[9];
    const float* ew   = (const float*)d_in[10];
    const float* eb   = (const float*)d_in[11];
    const float* aw   = (const float*)d_in[12];
    const float* ab   = (const float*)d_in[13];
    float* out = (float*)d_out;

    gemm_xw_kernel<<<dim3(8,32), 256>>>(ids, emb, wihf, wihb, bihf, bhhf, bihb, bhhb);
    lstm_kernel<<<128, 256>>>(whhf, whhb);
    head_kernel<<<64, 256>>>(ew, eb, aw, ab, out);
    scan_kernel<<<512, 128>>>(aw, out);
}

// round 5
// speedup vs baseline: 2.1994x; 1.0764x over previous
#include <cuda_runtime.h>
#include <cstdint>
#include <math.h>

#define B_ 32
#define L_ 128
#define D_ 300
#define H_ 128
#define E_ 34
#define A_ 36
#define M_ (B_*L_)          // 4096
#define NXW 1024
#define ARG_OFF (B_*L_*E_)  // 139264

// ------------------------- scratch (no allocs allowed) -----------------------
__device__ float g_xw[M_*NXW];       // x@W_ih^T + b_ih + b_hh, both dirs
__device__ float g_hidden[M_*256];   // [h_f | h_b]
__device__ float g_base[M_*A_];      // hidden@argW_h^T + arg_b
__device__ float g_trig[M_*A_];      // hidden@argW_t^T
__device__ int   g_evp[M_];          // argmax(event_logits)

// ------------------------- helpers ------------------------------------------
__device__ __forceinline__ unsigned long long pack2(float lo, float hi){
    unsigned long long r;
    asm("mov.b64 %0, {%1, %2};" : "=l"(r) : "f"(lo), "f"(hi));
    return r;
}
__device__ __forceinline__ void unpack2(unsigned long long v, float& lo, float& hi){
    asm("mov.b64 {%0, %1}, %2;" : "=f"(lo), "=f"(hi) : "l"(v));
}
__device__ __forceinline__ unsigned long long fma2(unsigned long long a,
                                                   unsigned long long b,
                                                   unsigned long long c){
    unsigned long long d;
    asm("fma.rn.f32x2 %0, %1, %2, %3;" : "=l"(d) : "l"(a), "l"(b), "l"(c));
    return d;
}
__device__ __forceinline__ uint32_t smem_u32(const void* p){
    return (uint32_t)__cvta_generic_to_shared(p);
}
__device__ __forceinline__ uint32_t mapa_u32(uint32_t a, uint32_t r){
    uint32_t d;
    asm("mapa.shared::cluster.u32 %0, %1, %2;" : "=r"(d) : "r"(a), "r"(r));
    return d;
}
__device__ __forceinline__ unsigned redux_max_u32(unsigned v){
    unsigned r; asm("redux.sync.max.u32 %0, %1, 0xffffffff;" : "=r"(r) : "r"(v)); return r;
}
// monotone float -> u32 order map
__device__ __forceinline__ unsigned fmap(float f){
    unsigned u = __float_as_uint(f);
    return (u & 0x80000000u) ? ~u : (u | 0x80000000u);
}
#define CLUSTER_SYNC_() do { \
    asm volatile("barrier.cluster.arrive.aligned;" ::: "memory"); \
    asm volatile("barrier.cluster.wait.aligned;"   ::: "memory"); \
} while(0)

// dummy kernel: steers the fixed ncu capture window (-s 5 -c 1) onto lstm
__global__ void noop_kernel() {}

// =============================================================================
// Kernel 1: xW = gather(emb, ids) @ [w_ih_f^T | w_ih_b^T] + (b_ih + b_hh)
// M=4096, N=1024, K=300.  128x128 tiles, 256 threads, 8x8 micro, f32x2 FMA.
// =============================================================================
__global__ __launch_bounds__(256) void gemm_xw_kernel(
    const int* __restrict__ ids, const float* __restrict__ emb,
    const float* __restrict__ wf, const float* __restrict__ wb,
    const float* __restrict__ bihf, const float* __restrict__ bhhf,
    const float* __restrict__ bihb, const float* __restrict__ bhhb)
{
    __shared__ float As[8][132];
    __shared__ float Bs[8][132];
    __shared__ int ids_s[128];

    int t  = threadIdx.x;
    int m0 = blockIdx.y * 128;
    int n0 = blockIdx.x * 128;

    const float* w;
    const float *b1, *b2;
    if (n0 < 512) { w = wf + (size_t)n0 * D_;        b1 = bihf + n0;        b2 = bhhf + n0; }
    else          { w = wb + (size_t)(n0-512) * D_;  b1 = bihb + (n0-512);  b2 = bhhb + (n0-512); }

    if (t < 128) ids_s[t] = ids[m0 + t];
    __syncthreads();

    int tx = t & 15, ty = t >> 4;
    unsigned long long acc[8][4];
#pragma unroll
    for (int r = 0; r < 8; r++)
#pragma unroll
        for (int p = 0; p < 4; p++) acc[r][p] = 0ull;

    int ai = t & 127, akk = (t >> 7) * 4;   // A loader: (row ai, kk akk..akk+3)
    int bj = t >> 3,  bkk = t & 7;          // B loader: (rows bj+32c, kk bkk)

    for (int k0 = 0; k0 < D_; k0 += 8) {
        const float* arow = emb + (size_t)ids_s[ai] * D_;
#pragma unroll
        for (int c = 0; c < 4; c++) {
            int kk = akk + c;
            As[kk][ai] = (k0 + kk < D_) ? arow[k0 + kk] : 0.f;
        }
#pragma unroll
        for (int c = 0; c < 4; c++) {
            int j = bj + 32 * c;
            Bs[bkk][j] = (k0 + bkk < D_) ? w[(size_t)j * D_ + k0 + bkk] : 0.f;
        }
        __syncthreads();
#pragma unroll
        for (int kk = 0; kk < 8; kk++) {
            float a_[8];
#pragma unroll
            for (int r = 0; r < 8; r++) a_[r] = As[kk][ty*8 + r];
            unsigned long long b2v[4];
            const float2* bp = (const float2*)&Bs[kk][tx*8];
#pragma unroll
            for (int p = 0; p < 4; p++) { float2 v = bp[p]; b2v[p] = pack2(v.x, v.y); }
#pragma unroll
            for (int r = 0; r < 8; r++) {
                unsigned long long a2 = pack2(a_[r], a_[r]);
#pragma unroll
                for (int p = 0; p < 4; p++) acc[r][p] = fma2(a2, b2v[p], acc[r][p]);
            }
        }
        __syncthreads();
    }

#pragma unroll
    for (int r = 0; r < 8; r++) {
        int m = m0 + ty*8 + r;
#pragma unroll
        for (int p = 0; p < 4; p++) {
            float lo, hi; unpack2(acc[r][p], lo, hi);
            int nlo = tx*8 + 2*p;
            g_xw[(size_t)m * NXW + n0 + nlo]     = lo + b1[nlo]   + b2[nlo];
            g_xw[(size_t)m * NXW + n0 + nlo + 1] = hi + b1[nlo+1] + b2[nlo+1];
        }
    }
}

// =============================================================================
// Kernel 2: BiLSTM recurrence.
// 32 clusters of 8 CTAs x 128 threads: cluster = (dir, batch-pair).
// CTA = 16 hidden units (64 gate rows) x 2 batches; K split 2-way (kq).
// W_hh slice = 64 scalar floats in registers. 256 small CTAs -> 2 per SM,
// so co-resident clusters hide each other's cluster.sync latency.
// =============================================================================
__global__ void __cluster_dims__(8,1,1) __launch_bounds__(128,2)
lstm_kernel(const float* __restrict__ whf, const float* __restrict__ whb)
{
    __shared__ __align__(16) float h_sm[2][2][132];   // [phase][batch][unit(+pad)]
    __shared__ float z_sm[2][64];                      // [batch][gate*16+uu]

    int bx   = blockIdx.x;
    int cid  = bx >> 3, rank = bx & 7;
    int dir  = cid & 1,  bp  = cid >> 1;      // batch pair: batches bp*2, bp*2+1
    int b0   = bp * 2;
    int u0   = rank * 16;

    int t = threadIdx.x, lane = t & 31, warp = t >> 5;
    int kq = lane >> 4, uu = lane & 15;
    int gate = warp;                          // 4 warps = 4 gates
    int grow = gate*H_ + u0 + uu;             // global gate row 0..511

    const float* whh = dir ? whb : whf;
    float w_reg[64];
    {
        const float4* wrow = (const float4*)(whh + (size_t)grow*H_ + kq*64);
#pragma unroll
        for (int i = 0; i < 16; i++) {
            float4 wv = wrow[i];
            w_reg[4*i]   = wv.x; w_reg[4*i+1] = wv.y;
            w_reg[4*i+2] = wv.z; w_reg[4*i+3] = wv.w;
        }
    }

    for (int idx = t; idx < 2*2*132; idx += 128) (&h_sm[0][0][0])[idx] = 0.f;

    int ub = t >> 4, uuu = t & 15;            // updater role (t < 32)
    float c_reg = 0.f;

    CLUSTER_SYNC_();                          // zeroed h visible cluster-wide

    int xw_col = dir*512 + grow;

    for (int s = 0; s < L_; s++) {
        int ph = s & 1;
        int tc = dir ? (L_-1-s) : s;

        float xwv0 = 0.f, xwv1 = 0.f;
        if (kq == 0) {
            size_t base = ((size_t)(b0)*L_ + tc) * NXW + xw_col;
            xwv0 = g_xw[base];
            xwv1 = g_xw[base + (size_t)L_*NXW];
        }

        const float4* h0 = (const float4*)&h_sm[ph][0][kq*64];
        const float4* h1 = (const float4*)&h_sm[ph][1][kq*64];
        float a0 = 0.f, a1 = 0.f;
#pragma unroll
        for (int i = 0; i < 16; i++) {
            float4 v0 = h0[i], v1 = h1[i];
            float w0 = w_reg[4*i], w1 = w_reg[4*i+1], w2 = w_reg[4*i+2], w3 = w_reg[4*i+3];
            a0 += w0*v0.x; a0 += w1*v0.y; a0 += w2*v0.z; a0 += w3*v0.w;
            a1 += w0*v1.x; a1 += w1*v1.y; a1 += w2*v1.z; a1 += w3*v1.w;
        }
        a0 += __shfl_xor_sync(~0u, a0, 16);
        a1 += __shfl_xor_sync(~0u, a1, 16);

        if (kq == 0) {
            z_sm[0][gate*16 + uu] = a0 + xwv0;
            z_sm[1][gate*16 + uu] = a1 + xwv1;
        }
        __syncthreads();

        if (t < 32) {
            float zi = z_sm[ub][uuu],      zf = z_sm[ub][16 + uuu];
            float zg = z_sm[ub][32 + uuu], zo = z_sm[ub][48 + uuu];
            float ig = 1.f / (1.f + expf(-zi));
            float fg = 1.f / (1.f + expf(-zf));
            float gg = tanhf(zg);
            float og = 1.f / (1.f + expf(-zo));
            c_reg = fg * c_reg + ig * gg;
            float h = og * tanhf(c_reg);

            int k = u0 + uuu;
            uint32_t loc = smem_u32(&h_sm[ph ^ 1][ub][k]);
#pragma unroll
            for (int r = 0; r < 8; r++) {
                uint32_t ra = mapa_u32(loc, (uint32_t)r);
                asm volatile("st.shared::cluster.f32 [%0], %1;" :: "r"(ra), "f"(h));
            }
            g_hidden[((size_t)((b0 + ub)*L_ + tc)) * 256 + dir*H_ + k] = h;
        }

        CLUSTER_SYNC_();
    }
}

// =============================================================================
// Kernel 3: fused head GEMM + event argmax.
// hidden[4096,256] @ W2^T, W2 rows = [event_w(34) | argW[:, :256](36) |
// argW[:,256:512](36)] -> 106 cols. Epilogue: argmax over 34 -> g_evp.
// =============================================================================
__global__ __launch_bounds__(256) void head_kernel(
    const float* __restrict__ ew, const float* __restrict__ eb,
    const float* __restrict__ aw, const float* __restrict__ ab,
    float* __restrict__ out)
{
    __shared__ float hsm[64][65];
    __shared__ float wsm[64][108];
    __shared__ float ev_sm[64][36];

    int t  = threadIdx.x;
    int m0 = blockIdx.x * 64;
    int ml = t >> 2, ng = t & 3;

    float acc[27];
#pragma unroll
    for (int c = 0; c < 27; c++) acc[c] = 0.f;

    for (int k0 = 0; k0 < 256; k0 += 64) {
        for (int idx = t; idx < 64*64; idx += 256) {
            int r = idx >> 6, c = idx & 63;
            hsm[r][c] = g_hidden[(size_t)(m0 + r)*256 + k0 + c];
        }
        for (int idx = t; idx < 64*108; idx += 256) {
            int kk = idx / 108, n = idx % 108;
            int k  = k0 + kk;
            float v = 0.f;
            if      (n < 34)  v = ew[(size_t)n*256 + k];
            else if (n < 70)  v = aw[(size_t)(n-34)*545 + k];
            else if (n < 106) v = aw[(size_t)(n-70)*545 + 256 + k];
            wsm[kk][n] = v;
        }
        __syncthreads();
#pragma unroll 8
        for (int kk = 0; kk < 64; kk++) {
            float hv = hsm[ml][kk];
#pragma unroll
            for (int c = 0; c < 27; c++) acc[c] += hv * wsm[kk][ng*27 + c];
        }
        __syncthreads();
    }

    int m = m0 + ml;
#pragma unroll
    for (int c = 0; c < 27; c++) {
        int n = ng*27 + c;
        if (n < 34) {
            float v = acc[c] + eb[n];
            out[(size_t)m*E_ + n] = v;
            ev_sm[ml][n] = v;
        }
        else if (n < 70)  g_base[(size_t)m*A_ + (n-34)] = acc[c] + ab[n-34];
        else if (n < 106) g_trig[(size_t)m*A_ + (n-70)] = acc[c];
    }
    __syncthreads();

    if (t < 64) {
        float bv = ev_sm[t][0]; int bi = 0;
#pragma unroll
        for (int e = 1; e < E_; e++) {
            float v = ev_sm[t][e];
            if (v > bv) { bv = v; bi = e; }
        }
        g_evp[m0 + t] = bi;
    }
}

// =============================================================================
// Kernel 4: scan. One warp per (b, l); g[b,l] is an independent 33-bit state.
// arg_logit[i] = base[b,l] + trig[b,i] + gW (incrementally maintained).
// Flip test: argmax>0  <=>  max_{j>0} v_j > v_0  -> one redux + parallel shfl.
// =============================================================================
__global__ __launch_bounds__(128) void scan_kernel(
    const float* __restrict__ aw, float* __restrict__ out)
{
    __shared__ float wg[36*33];   // arg_w[:, 512:545]
    int t = threadIdx.x;
    for (int idx = t; idx < 36*33; idx += 128) {
        int a = idx / 33, c = idx % 33;
        wg[idx] = aw[(size_t)a*545 + 512 + c];
    }
    __syncthreads();

    int gw_id = blockIdx.x * 4 + (t >> 5);
    int lane  = t & 31;
    int b = gw_id >> 7, l = gw_id & 127;
    size_t bl = (size_t)(b*L_ + l);

    // byte-pack this batch's 128 ev_preds: lane j holds evp[b, 4j..4j+3]
    const int* evb = g_evp + b*L_ + lane*4;
    int ep4 = evb[0] | (evb[1] << 8) | (evb[2] << 16) | (evb[3] << 24);

    bool hi = lane < 4;
    float base0 = g_base[bl*A_ + lane];
    float base1 = hi ? g_base[bl*A_ + 32 + lane] : -3.4e38f;
    float gw0 = 0.f, gw1 = 0.f;
    unsigned long long gb = 0ull;
    float* oarg = out + ARG_OFF;

    const float* trg = g_trig + (size_t)b*L_*A_;
    float t0 = trg[lane];
    float t1 = hi ? trg[32 + lane] : 0.f;

    for (int i = 0; i < L_; i++) {
        // prefetch next step's trig before the serial tail
        float t0n = 0.f, t1n = 0.f;
        if (i + 1 < L_) {
            t0n = trg[(i+1)*A_ + lane];
            if (hi) t1n = trg[(i+1)*A_ + 32 + lane];
        }

        float v0 = base0 + t0 + gw0;
        float v1 = hi ? (base1 + t1 + gw1) : -3.4e38f;

        size_t ob = ((size_t)(b*L_ + i)*L_ + l) * A_;
        oarg[ob + lane] = v0;
        if (hi) oarg[ob + 32 + lane] = v1;

        // rest-max (slots 1..35): lane 0 contributes only its slot-32 value
        float rest = (lane == 0) ? v1 : (hi ? fmaxf(v0, v1) : v0);
        unsigned m   = redux_max_u32(fmap(rest));           // serial: ~25 cyc
        float    v0b = __shfl_sync(0xffffffffu, v0, 0);     // runs alongside redux
        bool flip = m > fmap(v0b);

        int ep = (__shfl_sync(0xffffffffu, ep4, i >> 2) >> ((i & 3) * 8)) & 0xff;
        if (ep > 0 && flip) {
            int col = ep - 1;
            if (!((gb >> col) & 1ull)) {
                gb |= (1ull << col);
                gw0 += wg[lane*33 + col];
                if (hi) gw1 += wg[(32 + lane)*33 + col];
            }
        }
        t0 = t0n; t1 = t1n;
    }
}

// =============================================================================
extern "C" void kernel_launch(void* const* d_in, const int* in_sizes, int n_in,
                              void* d_out, int out_size)
{
    const int*   ids  = (const int*)  d_in[0];
    const float* emb  = (const float*)d_in[1];
    const float* wihf = (const float*)d_in[2];
    const float* whhf = (const float*)d_in[3];
    const float* bihf = (const float*)d_in[4];
    const float* bhhf = (const float*)d_in[5];
    const float* wihb = (const float*)d_in[6];
    const float* whhb = (const float*)d_in[7];
    const float* bihb = (const float*)d_in[8];
    const float* bhhb = (const float*)d_in[9];
    const float* ew   = (const float*)d_in[10];
    const float* eb   = (const float*)d_in[11];
    const float* aw   = (const float*)d_in[12];
    const float* ab   = (const float*)d_in[13];
    float* out = (float*)d_out;

    noop_kernel<<<1, 32>>>();   // shift ncu capture window (slot 6) onto lstm
    noop_kernel<<<1, 32>>>();
    gemm_xw_kernel<<<dim3(8,32), 256>>>(ids, emb, wihf, wihb, bihf, bhhf, bihb, bhhb);
    lstm_kernel<<<256, 128>>>(whhf, whhb);
    head_kernel<<<64, 256>>>(ew, eb, aw, ab, out);
    scan_kernel<<<1024, 128>>>(aw, out);
}